// round 9
// baseline (speedup 1.0000x reference)
#include <cuda_runtime.h>
#include <stdint.h>
#include <math.h>

#define Pw    7
#define PP    49
#define HEADS 8
#define DH    32
#define INNER 256
#define Cc    128
#define Bb    32
#define HW    56
#define WINS  2048
#define MROWS (WINS*PP)    // 100352

static __device__ float g_xw  [(size_t)MROWS * Cc];
static __device__ float g_qkv [(size_t)MROWS * 3 * INNER];
static __device__ float g_wqkv_t[768 * 128];
static __device__ float g_wout_t[256 * 128];
static __device__ float g_attn_dump[(size_t)WINS * HEADS * PP * PP];
static __device__ float g_o_dump  [(size_t)Bb * Cc * HW * HW];

__device__ __forceinline__ unsigned int f2tf32(float f) {
    unsigned int u; asm("cvt.rna.tf32.f32 %0, %1;" : "=r"(u) : "f"(f)); return u;
}
__device__ __forceinline__ float tf32r(float f) { return __uint_as_float(f2tf32(f)); }

__device__ __forceinline__ void mma_tf32(float c[4],
    unsigned int a0, unsigned int a1, unsigned int a2, unsigned int a3,
    unsigned int b0, unsigned int b1)
{
    asm volatile(
        "mma.sync.aligned.m16n8k8.row.col.f32.tf32.tf32.f32 "
        "{%0,%1,%2,%3}, {%4,%5,%6,%7}, {%8,%9}, {%0,%1,%2,%3};"
        : "+f"(c[0]), "+f"(c[1]), "+f"(c[2]), "+f"(c[3])
        : "r"(a0), "r"(a1), "r"(a2), "r"(a3), "r"(b0), "r"(b1));
}

__device__ __forceinline__ void cp16(unsigned int saddr, const void* gaddr) {
    asm volatile("cp.async.cg.shared.global [%0], [%1], 16;" :: "r"(saddr), "l"(gaddr));
}
__device__ __forceinline__ void cp_commit() { asm volatile("cp.async.commit_group;"); }
__device__ __forceinline__ void cp_wait1()  { asm volatile("cp.async.wait_group 1;"); }
__device__ __forceinline__ void cp_wait0()  { asm volatile("cp.async.wait_group 0;"); }

__device__ __forceinline__ float4 tf32r4(float4 v) {
    return make_float4(tf32r(v.x), tf32r(v.y), tf32r(v.z), tf32r(v.w));
}

// ---------------------------------------------------------------------------
// Kernel 0: transpose + tf32-round weights (tiny)
// ---------------------------------------------------------------------------
__global__ void transpose_w(const float* __restrict__ wq, const float* __restrict__ wo)
{
    int idx = blockIdx.x * 256 + threadIdx.x;
    if (idx < 768 * 128) {
        int k = idx / 768, n = idx - k * 768;
        g_wqkv_t[idx] = tf32r(wq[n * 128 + k]);
    }
    int i2 = idx - 768 * 128;
    if (i2 >= 0 && i2 < 256 * 128) {
        int k = i2 / 128, n = i2 - k * 128;
        g_wout_t[i2] = tf32r(wo[n * 256 + k]);
    }
}

// ---------------------------------------------------------------------------
// Kernel 1: gather (roll -3,-3 + window partition) -> g_xw, tf32-rounded.
// ---------------------------------------------------------------------------
__global__ void gather_x(const float* __restrict__ x)
{
    __shared__ float sm[128][65];
    const int b  = blockIdx.x / 49;
    const int p0 = (blockIdx.x - b * 49) * 64;
    const int tid = threadIdx.x;

    for (int i = tid; i < 128 * 64; i += 256) {
        int c = i >> 6, p = i & 63;
        sm[c][p] = x[((size_t)b * 128 + c) * 3136 + p0 + p];
    }
    __syncthreads();
    for (int i = tid; i < 64 * 128; i += 256) {
        int p = i >> 7, c = i & 127;
        int pix = p0 + p;
        int h = pix / HW, w = pix - h * HW;
        int hs = h - 3; if (hs < 0) hs += HW;
        int ws = w - 3; if (ws < 0) ws += HW;
        int win = b * 64 + (hs / Pw) * 8 + (ws / Pw);
        int t   = (hs % Pw) * Pw + (ws % Pw);
        g_xw[((size_t)win * PP + t) * Cc + c] = tf32r(sm[c][p]);
    }
}

// ---------------------------------------------------------------------------
// Kernel 2: QKV GEMM, tf32 TC, 3-stage cp.async (unchanged from R8)
// ---------------------------------------------------------------------------
__global__ void qkv_gemm_tc()
{
    __shared__ float As[3][128][20];
    __shared__ float Bs[3][16][136];
    const unsigned int A_STRIDE = 128 * 20 * 4;
    const unsigned int B_STRIDE = 16 * 136 * 4;

    const int tid  = threadIdx.x;
    const int bm   = blockIdx.y * 128;
    const int bn   = blockIdx.x * 128;
    const int lane = tid & 31, wid = tid >> 5;
    const int wm   = (wid & 1) * 64, wn = (wid >> 1) * 32;

    const int ar = tid & 127, ak = (tid >> 7) * 4;
    const float* agp = g_xw + (size_t)(bm + ar) * Cc + ak;
    const int bk = tid >> 4, bn8 = (tid & 15) * 8;
    const float* bgp = g_wqkv_t + (size_t)bk * 768 + bn + bn8;

    unsigned int sA = (unsigned int)__cvta_generic_to_shared(&As[0][ar][ak]);
    unsigned int sB = (unsigned int)__cvta_generic_to_shared(&Bs[0][bk][bn8]);

    float acc[4][4][4];
    #pragma unroll
    for (int i = 0; i < 4; i++)
        #pragma unroll
        for (int j = 0; j < 4; j++)
            #pragma unroll
            for (int c = 0; c < 4; c++) acc[i][j][c] = 0.f;

    #pragma unroll
    for (int s = 0; s < 2; s++) {
        const int k0 = s * 16;
        cp16(sA + s * A_STRIDE,      agp + k0);
        cp16(sA + s * A_STRIDE + 32, agp + k0 + 8);
        cp16(sB + s * B_STRIDE,      bgp + (size_t)k0 * 768);
        cp16(sB + s * B_STRIDE + 16, bgp + (size_t)k0 * 768 + 4);
        cp_commit();
    }

    #pragma unroll
    for (int ks = 0; ks < 8; ks++) {
        if (ks < 7) cp_wait1(); else cp_wait0();
        __syncthreads();
        const int st = ks % 3;
        #pragma unroll
        for (int k8 = 0; k8 < 16; k8 += 8) {
            unsigned int af[4][4], bf[4][2];
            const int kk = k8 + (lane & 3);
            #pragma unroll
            for (int mt = 0; mt < 4; mt++) {
                int r = wm + mt * 16 + (lane >> 2);
                af[mt][0] = __float_as_uint(As[st][r][kk]);
                af[mt][1] = __float_as_uint(As[st][r + 8][kk]);
                af[mt][2] = __float_as_uint(As[st][r][kk + 4]);
                af[mt][3] = __float_as_uint(As[st][r + 8][kk + 4]);
            }
            #pragma unroll
            for (int nt = 0; nt < 4; nt++) {
                int c = wn + nt * 8 + (lane >> 2);
                bf[nt][0] = __float_as_uint(Bs[st][kk][c]);
                bf[nt][1] = __float_as_uint(Bs[st][kk + 4][c]);
            }
            #pragma unroll
            for (int mt = 0; mt < 4; mt++)
                #pragma unroll
                for (int nt = 0; nt < 4; nt++)
                    mma_tf32(acc[mt][nt], af[mt][0], af[mt][1], af[mt][2], af[mt][3],
                             bf[nt][0], bf[nt][1]);
        }
        __syncthreads();
        if (ks + 2 < 8) {
            const int snew = (ks + 2) % 3;
            const int k0 = (ks + 2) * 16;
            cp16(sA + snew * A_STRIDE,      agp + k0);
            cp16(sA + snew * A_STRIDE + 32, agp + k0 + 8);
            cp16(sB + snew * B_STRIDE,      bgp + (size_t)k0 * 768);
            cp16(sB + snew * B_STRIDE + 16, bgp + (size_t)k0 * 768 + 4);
            cp_commit();
        }
    }

    #pragma unroll
    for (int mt = 0; mt < 4; mt++) {
        int r0 = bm + wm + mt * 16 + (lane >> 2);
        #pragma unroll
        for (int nt = 0; nt < 4; nt++) {
            int c = bn + wn + nt * 8 + (lane & 3) * 2;
            *(float2*)&g_qkv[(size_t)r0 * 768 + c] =
                make_float2(acc[mt][nt][0], acc[mt][nt][1]);
            *(float2*)&g_qkv[(size_t)(r0 + 8) * 768 + c] =
                make_float2(acc[mt][nt][2], acc[mt][nt][3]);
        }
    }
}

// ---------------------------------------------------------------------------
// Kernel 3: FUSED attention + output projection. Block = window, 256 thr.
// Warps 0-3 process head 2h, warps 4-7 head 2h+1, 4 pair-iterations.
// Then out = osm @ w_out^T + bias, scattered with w-fastest coalescing.
// ---------------------------------------------------------------------------
// smem float offsets
#define OSM_OFF 0                      // [49][260]
#define QSM_OFF 12740                  // [2][49][36]
#define KSM_OFF (QSM_OFF + 3528)       // [2][56][40]
#define VSM_OFF (KSM_OFF + 4480)       // [2][56][40]
#define SSM_OFF (VSM_OFF + 4480)       // [2][49][60]
#define WSM_OFF (SSM_OFF + 5880)       // [64][136]
#define PSM_OFF (WSM_OFF + 8704)       // [169]
#define BSM_OFF (PSM_OFF + 169)        // [128]
#define SMEM_FLOATS (BSM_OFF + 128)    // 40109 -> 160436 B

__global__ void __launch_bounds__(256) fused_attn_out(
    const float* __restrict__ pos, const float* __restrict__ b_out,
    float* __restrict__ attn_out, float* __restrict__ out)
{
    extern __shared__ float smp[];
    float* osm = smp + OSM_OFF;        // stride 260 (≡4 mod 32)
    float* qsmb = smp + QSM_OFF;       // per-pg stride 1764, row stride 36
    float* ksmb = smp + KSM_OFF;       // per-pg stride 2240, row stride 40
    float* vsmb = smp + VSM_OFF;
    float* ssmb = smp + SSM_OFF;       // per-pg stride 2940, row stride 60
    float* wsm  = smp + WSM_OFF;       // [64][136]
    float* psm  = smp + PSM_OFF;
    float* bsm  = smp + BSM_OFF;
    float* rsm  = smp + QSM_OFF;       // alias: [49][132] staging (18368 floats avail)

    const int win  = blockIdx.x;
    const int wl   = win & 63;
    const bool ul = (wl >= 56);
    const bool lr = (wl == 55) || (wl == 63);

    const int tid  = threadIdx.x;
    const int lane = tid & 31;
    const int wid  = tid >> 5;
    const int pg   = wid >> 2;         // head-pair group 0/1
    const int wpg  = wid & 3;          // warp within group
    const int gtid = tid & 127;
    const int wm   = wpg * 16;
    const int qr   = lane >> 2;
    const int ql   = lane & 3;

    const float* qkvb = g_qkv + (size_t)win * PP * 768;

    // one-time loads
    for (int idx = tid; idx < 169; idx += 256) psm[idx] = pos[idx];
    for (int idx = tid; idx < 128; idx += 256) bsm[idx] = b_out[idx];
    for (int idx = tid; idx < 2 * 7 * 40; idx += 256) {
        int g = idx / 280, rem = idx - g * 280;
        ksmb[g * 2240 + (49 + rem / 40) * 40 + rem % 40] = 0.f;
        vsmb[g * 2240 + (49 + rem / 40) * 40 + rem % 40] = 0.f;
    }

    const int rA = wm + qr, rB = rA + 8;
    const bool vA = (rA < PP), vB = (rB < PP);
    const int iA = vA ? rA : 48;
    const int iB = vB ? rB : 48;
    const int xiA = iA / Pw, yiA = iA - xiA * Pw;
    const int xiB = iB / Pw, yiB = iB - xiB * Pw;
    const float scale = 0.1767766952966369f;

    float* qsm = qsmb + pg * 1764;
    float* ksm = ksmb + pg * 2240;
    float* vsm = vsmb + pg * 2240;
    float* ssm = ssmb + pg * 2940;

    for (int hp = 0; hp < 4; hp++) {
        __syncthreads();   // buffers free from previous iteration

        // cooperative load of q/k/v for both heads of the pair
        for (int idx = tid; idx < PP * 16; idx += 256) {
            const int j  = idx >> 4;
            const int f4 = idx & 15;
            const int g  = f4 >> 3;          // which head of pair
            const int d  = (f4 & 7) * 4;
            const float* row = qkvb + (size_t)j * 768 + hp * 64 + f4 * 4;
            float4 qv = *(const float4*)(row);
            float4 kv = *(const float4*)(row + 256);
            float4 vv = *(const float4*)(row + 512);
            *(float4*)&qsmb[g * 1764 + j * 36 + d] = tf32r4(qv);
            *(float4*)&ksmb[g * 2240 + j * 40 + d] = tf32r4(kv);
            *(float4*)&vsmb[g * 2240 + j * 40 + d] = tf32r4(vv);
        }
        __syncthreads();

        const int head = hp * 2 + pg;

        // ---- S = Q @ K^T ----
        float s[7][4];
        #pragma unroll
        for (int nt = 0; nt < 7; nt++)
            #pragma unroll
            for (int c = 0; c < 4; c++) s[nt][c] = 0.f;

        #pragma unroll
        for (int ks = 0; ks < 4; ks++) {
            const int kk = ks * 8 + ql;
            unsigned int a[4], b[7][2];
            a[0] = vA ? __float_as_uint(qsm[rA * 36 + kk])     : 0u;
            a[1] = vB ? __float_as_uint(qsm[rB * 36 + kk])     : 0u;
            a[2] = vA ? __float_as_uint(qsm[rA * 36 + kk + 4]) : 0u;
            a[3] = vB ? __float_as_uint(qsm[rB * 36 + kk + 4]) : 0u;
            #pragma unroll
            for (int nt = 0; nt < 7; nt++) {
                int c = nt * 8 + qr;
                b[nt][0] = __float_as_uint(ksm[c * 40 + kk]);
                b[nt][1] = __float_as_uint(ksm[c * 40 + kk + 4]);
            }
            #pragma unroll
            for (int nt = 0; nt < 7; nt++)
                mma_tf32(s[nt], a[0], a[1], a[2], a[3], b[nt][0], b[nt][1]);
        }

        // ---- bias + masks + softmax ----
        #pragma unroll
        for (int nt = 0; nt < 7; nt++) {
            #pragma unroll
            for (int e = 0; e < 4; e++) {
                int j  = nt * 8 + ql * 2 + (e & 1);
                int xi = (e < 2) ? xiA : xiB;
                int yi = (e < 2) ? yiA : yiB;
                int r  = (e < 2) ? rA : rB;
                int jc = (j < PP) ? j : 48;
                int xj = jc / Pw, yj = jc - xj * Pw;
                float val = s[nt][e] * scale + psm[(xj - xi + 6) * 13 + (yj - yi + 6)];
                if (j >= PP) val = -1e30f;
                if (ul && ((r >= 28) != (j >= 28))) val = -1e30f;
                if (lr && ((yi >= 4) != (yj >= 4))) val = -1e30f;
                s[nt][e] = val;
            }
        }
        float mA = -1e30f, mB = -1e30f;
        #pragma unroll
        for (int nt = 0; nt < 7; nt++) {
            mA = fmaxf(mA, fmaxf(s[nt][0], s[nt][1]));
            mB = fmaxf(mB, fmaxf(s[nt][2], s[nt][3]));
        }
        mA = fmaxf(mA, __shfl_xor_sync(0xffffffffu, mA, 1));
        mA = fmaxf(mA, __shfl_xor_sync(0xffffffffu, mA, 2));
        mB = fmaxf(mB, __shfl_xor_sync(0xffffffffu, mB, 1));
        mB = fmaxf(mB, __shfl_xor_sync(0xffffffffu, mB, 2));

        float sA = 0.f, sB = 0.f;
        #pragma unroll
        for (int nt = 0; nt < 7; nt++) {
            s[nt][0] = __expf(s[nt][0] - mA);
            s[nt][1] = __expf(s[nt][1] - mA);
            s[nt][2] = __expf(s[nt][2] - mB);
            s[nt][3] = __expf(s[nt][3] - mB);
            sA += s[nt][0] + s[nt][1];
            sB += s[nt][2] + s[nt][3];
        }
        sA += __shfl_xor_sync(0xffffffffu, sA, 1);
        sA += __shfl_xor_sync(0xffffffffu, sA, 2);
        sB += __shfl_xor_sync(0xffffffffu, sB, 1);
        sB += __shfl_xor_sync(0xffffffffu, sB, 2);
        const float iAu = 1.0f / sA, iBu = 1.0f / sB;

        #pragma unroll
        for (int nt = 0; nt < 7; nt++) {
            int j0 = nt * 8 + ql * 2;
            if (vA) *(float2*)&ssm[rA * 60 + j0] = make_float2(s[nt][0] * iAu, s[nt][1] * iAu);
            if (vB) *(float2*)&ssm[rB * 60 + j0] = make_float2(s[nt][2] * iBu, s[nt][3] * iBu);
        }
        __syncthreads();

        // attn gmem write (each group writes its head)
        float* aout = attn_out + ((size_t)(win * 8 + head)) * (PP * PP);
        for (int idx = gtid; idx < PP * PP; idx += 128) {
            int r = idx / PP;
            aout[idx] = ssm[r * 60 + (idx - r * PP)];
        }

        // ---- O = P @ V -> osm columns head*32.. ----
        float o[4][4];
        #pragma unroll
        for (int nt = 0; nt < 4; nt++)
            #pragma unroll
            for (int c = 0; c < 4; c++) o[nt][c] = 0.f;

        #pragma unroll
        for (int ks = 0; ks < 7; ks++) {
            const int kk = ks * 8 + ql;
            unsigned int a[4], b[4][2];
            a[0] = vA ? f2tf32(ssm[rA * 60 + kk])     : 0u;
            a[1] = vB ? f2tf32(ssm[rB * 60 + kk])     : 0u;
            a[2] = vA ? f2tf32(ssm[rA * 60 + kk + 4]) : 0u;
            a[3] = vB ? f2tf32(ssm[rB * 60 + kk + 4]) : 0u;
            #pragma unroll
            for (int nt = 0; nt < 4; nt++) {
                int c = nt * 8 + qr;
                b[nt][0] = __float_as_uint(vsm[kk * 40 + c]);
                b[nt][1] = __float_as_uint(vsm[(kk + 4) * 40 + c]);
            }
            #pragma unroll
            for (int nt = 0; nt < 4; nt++)
                mma_tf32(o[nt], a[0], a[1], a[2], a[3], b[nt][0], b[nt][1]);
        }

        const int hc = head * 32;
        #pragma unroll
        for (int nt = 0; nt < 4; nt++) {
            int c = hc + nt * 8 + ql * 2;
            if (vA) *(float2*)&osm[rA * 260 + c] =
                make_float2(tf32r(o[nt][0]), tf32r(o[nt][1]));
            if (vB) *(float2*)&osm[rB * 260 + c] =
                make_float2(tf32r(o[nt][2]), tf32r(o[nt][3]));
        }
    }

    // =========== final out GEMM: rsm = osm[49x256] @ w_out^T + bias =========
    const int wm2 = (wid & 3) * 16;
    const int wn2 = (wid >> 2) * 64;
    const int r2A = wm2 + qr, r2B = r2A + 8;
    const bool v2A = (r2A < PP), v2B = (r2B < PP);

    float acc2[8][4];
    #pragma unroll
    for (int nt = 0; nt < 8; nt++)
        #pragma unroll
        for (int c = 0; c < 4; c++) acc2[nt][c] = 0.f;

    for (int kc = 0; kc < 4; kc++) {
        __syncthreads();
        // load weight chunk [64][128] -> wsm stride 136
        for (int idx = tid; idx < 64 * 32; idx += 256) {
            int kk = idx >> 5, n4 = (idx & 31) * 4;
            float4 wv = *(const float4*)&g_wout_t[(size_t)(kc * 64 + kk) * 128 + n4];
            *(float4*)&wsm[kk * 136 + n4] = wv;
        }
        __syncthreads();

        #pragma unroll
        for (int k8 = 0; k8 < 64; k8 += 8) {
            const int kk = k8 + ql;
            const int kg = kc * 64 + kk;
            unsigned int a[4], b[8][2];
            a[0] = v2A ? __float_as_uint(osm[r2A * 260 + kg])     : 0u;
            a[1] = v2B ? __float_as_uint(osm[r2B * 260 + kg])     : 0u;
            a[2] = v2A ? __float_as_uint(osm[r2A * 260 + kg + 4]) : 0u;
            a[3] = v2B ? __float_as_uint(osm[r2B * 260 + kg + 4]) : 0u;
            #pragma unroll
            for (int nt = 0; nt < 8; nt++) {
                int c = wn2 + nt * 8 + qr;
                b[nt][0] = __float_as_uint(wsm[kk * 136 + c]);
                b[nt][1] = __float_as_uint(wsm[(kk + 4) * 136 + c]);
            }
            #pragma unroll
            for (int nt = 0; nt < 8; nt++)
                mma_tf32(acc2[nt], a[0], a[1], a[2], a[3], b[nt][0], b[nt][1]);
        }
    }
    __syncthreads();   // osm reads done; rsm (aliased) safe to write

    #pragma unroll
    for (int nt = 0; nt < 8; nt++) {
        int c = wn2 + nt * 8 + ql * 2;
        float b0 = bsm[c], b1 = bsm[c + 1];
        if (v2A) *(float2*)&rsm[r2A * 132 + c] =
            make_float2(acc2[nt][0] + b0, acc2[nt][1] + b1);
        if (v2B) *(float2*)&rsm[r2B * 132 + c] =
            make_float2(acc2[nt][2] + b0, acc2[nt][3] + b1);
    }
    __syncthreads();

    // scatter with roll(+3,+3), w-fastest for 28B-contiguous stores
    const int b   = win >> 6;
    const int i1  = (wl >> 3), i2 = (wl & 7);
    for (int idx = tid; idx < PP * 128; idx += 256) {
        int c = idx / PP;
        int t = idx - c * PP;
        int xx = t / Pw, yy = t - xx * Pw;
        int h = i1 * Pw + xx + 3; if (h >= HW) h -= HW;
        int w = i2 * Pw + yy + 3; if (w >= HW) w -= HW;
        out[((size_t)b * 128 + c) * 3136 + h * HW + w] = rsm[t * 132 + c];
    }
}

// ---------------------------------------------------------------------------
extern "C" void kernel_launch(void* const* d_in, const int* in_sizes, int n_in,
                              void* d_out, int out_size)
{
    const float* x      = (const float*)d_in[0];
    const float* w_qkv  = (const float*)d_in[1];
    const float* w_out  = (const float*)d_in[2];
    const float* b_out  = (const float*)d_in[3];
    const float* pos    = (const float*)d_in[4];

    const long long O_ELEMS = (long long)Bb * Cc * HW * HW;
    const long long A_ELEMS = (long long)WINS * HEADS * PP * PP;

    float* outp = (float*)d_out;
    float* o_ptr;
    float* attn_ptr;

    if ((long long)out_size >= O_ELEMS + A_ELEMS) {
        o_ptr    = outp;
        attn_ptr = outp + O_ELEMS;
    } else if ((long long)out_size == A_ELEMS) {
        attn_ptr = outp;
        cudaGetSymbolAddress((void**)&o_ptr, g_o_dump);
    } else {
        o_ptr = outp;
        cudaGetSymbolAddress((void**)&attn_ptr, g_attn_dump);
    }

    static int smem_set = 0;
    if (!smem_set) {
        cudaFuncSetAttribute(fused_attn_out,
                             cudaFuncAttributeMaxDynamicSharedMemorySize,
                             SMEM_FLOATS * 4);
        smem_set = 1;
    }

    transpose_w<<<512, 256>>>(w_qkv, w_out);
    gather_x<<<Bb * 49, 256>>>(x);
    qkv_gemm_tc<<<dim3(768 / 128, MROWS / 128), 256>>>();
    fused_attn_out<<<WINS, 256, SMEM_FLOATS * 4>>>(pos, b_out, attn_ptr, o_ptr);
}

// round 10
// speedup vs baseline: 1.4648x; 1.4648x over previous
#include <cuda_runtime.h>
#include <stdint.h>
#include <math.h>

#define Pw    7
#define PP    49
#define HEADS 8
#define DH    32
#define INNER 256
#define Cc    128
#define Bb    32
#define HW    56
#define WINS  2048
#define MROWS (WINS*PP)    // 100352

static __device__ float g_xw  [(size_t)MROWS * Cc];
static __device__ float g_qkv [(size_t)MROWS * 3 * INNER];
static __device__ float g_omid[(size_t)MROWS * INNER];
static __device__ float g_wqkv_t[768 * 128];
static __device__ float g_wout_t[256 * 128];
static __device__ float g_attn_dump[(size_t)WINS * HEADS * PP * PP];
static __device__ float g_o_dump  [(size_t)Bb * Cc * HW * HW];

__device__ __forceinline__ unsigned int f2tf32(float f) {
    unsigned int u; asm("cvt.rna.tf32.f32 %0, %1;" : "=r"(u) : "f"(f)); return u;
}
__device__ __forceinline__ float tf32r(float f) { return __uint_as_float(f2tf32(f)); }

__device__ __forceinline__ void mma_tf32(float c[4],
    unsigned int a0, unsigned int a1, unsigned int a2, unsigned int a3,
    unsigned int b0, unsigned int b1)
{
    asm volatile(
        "mma.sync.aligned.m16n8k8.row.col.f32.tf32.tf32.f32 "
        "{%0,%1,%2,%3}, {%4,%5,%6,%7}, {%8,%9}, {%0,%1,%2,%3};"
        : "+f"(c[0]), "+f"(c[1]), "+f"(c[2]), "+f"(c[3])
        : "r"(a0), "r"(a1), "r"(a2), "r"(a3), "r"(b0), "r"(b1));
}

__device__ __forceinline__ void cp16(unsigned int saddr, const void* gaddr) {
    asm volatile("cp.async.cg.shared.global [%0], [%1], 16;" :: "r"(saddr), "l"(gaddr));
}
__device__ __forceinline__ void cp_commit() { asm volatile("cp.async.commit_group;"); }
__device__ __forceinline__ void cp_wait1()  { asm volatile("cp.async.wait_group 1;"); }
__device__ __forceinline__ void cp_wait0()  { asm volatile("cp.async.wait_group 0;"); }

__device__ __forceinline__ float4 tf32r4(float4 v) {
    return make_float4(tf32r(v.x), tf32r(v.y), tf32r(v.z), tf32r(v.w));
}

// ---------------------------------------------------------------------------
// Kernel 0: transpose + tf32-round weights (tiny)
// ---------------------------------------------------------------------------
__global__ void transpose_w(const float* __restrict__ wq, const float* __restrict__ wo)
{
    int idx = blockIdx.x * 256 + threadIdx.x;
    if (idx < 768 * 128) {
        int k = idx / 768, n = idx - k * 768;
        g_wqkv_t[idx] = tf32r(wq[n * 128 + k]);
    }
    int i2 = idx - 768 * 128;
    if (i2 >= 0 && i2 < 256 * 128) {
        int k = i2 / 128, n = i2 - k * 128;
        g_wout_t[i2] = tf32r(wo[n * 256 + k]);
    }
}

// ---------------------------------------------------------------------------
// Kernel 1: gather (roll -3,-3 + window partition) -> g_xw, tf32-rounded.
// ---------------------------------------------------------------------------
__global__ void gather_x(const float* __restrict__ x)
{
    __shared__ float sm[128][65];
    const int b  = blockIdx.x / 49;
    const int p0 = (blockIdx.x - b * 49) * 64;
    const int tid = threadIdx.x;

    for (int i = tid; i < 128 * 64; i += 256) {
        int c = i >> 6, p = i & 63;
        sm[c][p] = x[((size_t)b * 128 + c) * 3136 + p0 + p];
    }
    __syncthreads();
    for (int i = tid; i < 64 * 128; i += 256) {
        int p = i >> 7, c = i & 127;
        int pix = p0 + p;
        int h = pix / HW, w = pix - h * HW;
        int hs = h - 3; if (hs < 0) hs += HW;
        int ws = w - 3; if (ws < 0) ws += HW;
        int win = b * 64 + (hs / Pw) * 8 + (ws / Pw);
        int t   = (hs % Pw) * Pw + (ws % Pw);
        g_xw[((size_t)win * PP + t) * Cc + c] = tf32r(sm[c][p]);
    }
}

// ---------------------------------------------------------------------------
// Kernel 2: QKV GEMM, tf32 TC, 3-stage cp.async (unchanged from R8)
// ---------------------------------------------------------------------------
__global__ void qkv_gemm_tc()
{
    __shared__ float As[3][128][20];
    __shared__ float Bs[3][16][136];
    const unsigned int A_STRIDE = 128 * 20 * 4;
    const unsigned int B_STRIDE = 16 * 136 * 4;

    const int tid  = threadIdx.x;
    const int bm   = blockIdx.y * 128;
    const int bn   = blockIdx.x * 128;
    const int lane = tid & 31, wid = tid >> 5;
    const int wm   = (wid & 1) * 64, wn = (wid >> 1) * 32;

    const int ar = tid & 127, ak = (tid >> 7) * 4;
    const float* agp = g_xw + (size_t)(bm + ar) * Cc + ak;
    const int bk = tid >> 4, bn8 = (tid & 15) * 8;
    const float* bgp = g_wqkv_t + (size_t)bk * 768 + bn + bn8;

    unsigned int sA = (unsigned int)__cvta_generic_to_shared(&As[0][ar][ak]);
    unsigned int sB = (unsigned int)__cvta_generic_to_shared(&Bs[0][bk][bn8]);

    float acc[4][4][4];
    #pragma unroll
    for (int i = 0; i < 4; i++)
        #pragma unroll
        for (int j = 0; j < 4; j++)
            #pragma unroll
            for (int c = 0; c < 4; c++) acc[i][j][c] = 0.f;

    #pragma unroll
    for (int s = 0; s < 2; s++) {
        const int k0 = s * 16;
        cp16(sA + s * A_STRIDE,      agp + k0);
        cp16(sA + s * A_STRIDE + 32, agp + k0 + 8);
        cp16(sB + s * B_STRIDE,      bgp + (size_t)k0 * 768);
        cp16(sB + s * B_STRIDE + 16, bgp + (size_t)k0 * 768 + 4);
        cp_commit();
    }

    #pragma unroll
    for (int ks = 0; ks < 8; ks++) {
        if (ks < 7) cp_wait1(); else cp_wait0();
        __syncthreads();
        const int st = ks % 3;
        #pragma unroll
        for (int k8 = 0; k8 < 16; k8 += 8) {
            unsigned int af[4][4], bf[4][2];
            const int kk = k8 + (lane & 3);
            #pragma unroll
            for (int mt = 0; mt < 4; mt++) {
                int r = wm + mt * 16 + (lane >> 2);
                af[mt][0] = __float_as_uint(As[st][r][kk]);
                af[mt][1] = __float_as_uint(As[st][r + 8][kk]);
                af[mt][2] = __float_as_uint(As[st][r][kk + 4]);
                af[mt][3] = __float_as_uint(As[st][r + 8][kk + 4]);
            }
            #pragma unroll
            for (int nt = 0; nt < 4; nt++) {
                int c = wn + nt * 8 + (lane >> 2);
                bf[nt][0] = __float_as_uint(Bs[st][kk][c]);
                bf[nt][1] = __float_as_uint(Bs[st][kk + 4][c]);
            }
            #pragma unroll
            for (int mt = 0; mt < 4; mt++)
                #pragma unroll
                for (int nt = 0; nt < 4; nt++)
                    mma_tf32(acc[mt][nt], af[mt][0], af[mt][1], af[mt][2], af[mt][3],
                             bf[nt][0], bf[nt][1]);
        }
        __syncthreads();
        if (ks + 2 < 8) {
            const int snew = (ks + 2) % 3;
            const int k0 = (ks + 2) * 16;
            cp16(sA + snew * A_STRIDE,      agp + k0);
            cp16(sA + snew * A_STRIDE + 32, agp + k0 + 8);
            cp16(sB + snew * B_STRIDE,      bgp + (size_t)k0 * 768);
            cp16(sB + snew * B_STRIDE + 16, bgp + (size_t)k0 * 768 + 4);
            cp_commit();
        }
    }

    #pragma unroll
    for (int mt = 0; mt < 4; mt++) {
        int r0 = bm + wm + mt * 16 + (lane >> 2);
        #pragma unroll
        for (int nt = 0; nt < 4; nt++) {
            int c = bn + wn + nt * 8 + (lane & 3) * 2;
            *(float2*)&g_qkv[(size_t)r0 * 768 + c] =
                make_float2(acc[mt][nt][0], acc[mt][nt][1]);
            *(float2*)&g_qkv[(size_t)(r0 + 8) * 768 + c] =
                make_float2(acc[mt][nt][2], acc[mt][nt][3]);
        }
    }
}

// ---------------------------------------------------------------------------
// Kernel 3: TC attention (R8 structure), qsm/ssm aliased to shrink smem.
// ---------------------------------------------------------------------------
#define QSM(r,c) usm[(r) * 36 + (c)]
#define SSM(r,c) usm[(r) * 60 + (c)]

__global__ void __launch_bounds__(128, 7) attn_tc_kernel(const float* __restrict__ pos,
                                                         float* __restrict__ attn_out)
{
    const int blk  = blockIdx.x;
    const int win  = blk >> 3;
    const int head = blk & 7;
    const int wl   = win & 63;
    const bool ul = (wl >= 56);
    const bool lr = (wl == 55) || (wl == 63);

    __shared__ float usm[49 * 60];   // union: Q [49][36] then P [49][60]
    __shared__ float ksm[56][40];    // K row-major [j][d]
    __shared__ float vsm[56][40];    // V [j][d]
    __shared__ float psm[169];

    const int tid  = threadIdx.x;
    const int lane = tid & 31;
    const int warp = tid >> 5;
    const int wm   = warp * 16;
    const int qr   = lane >> 2;
    const int ql   = lane & 3;

    const float* qb = g_qkv + (size_t)win * PP * 768 + head * 32;

    for (int idx = tid; idx < 7 * 40; idx += 128) {
        ksm[49 + idx / 40][idx % 40] = 0.f;
        vsm[49 + idx / 40][idx % 40] = 0.f;
    }
    for (int idx = tid; idx < 169; idx += 128) psm[idx] = pos[idx];

    // fused float4 load of q/k/v rows
    for (int idx = tid; idx < PP * 8; idx += 128) {
        const int j = idx >> 3, f = (idx & 7) * 4;
        const float* row = qb + (size_t)j * 768 + f;
        float4 qv = *(const float4*)(row);
        float4 kv = *(const float4*)(row + 256);
        float4 vv = *(const float4*)(row + 512);
        *(float4*)&QSM(j, f) = tf32r4(qv);
        *(float4*)&ksm[j][f] = tf32r4(kv);
        *(float4*)&vsm[j][f] = tf32r4(vv);
    }
    __syncthreads();

    const int rA = wm + qr, rB = rA + 8;
    const bool vA = (rA < PP), vB = (rB < PP);

    // ---- S = Q @ K^T ----
    float s[7][4];
    #pragma unroll
    for (int nt = 0; nt < 7; nt++)
        #pragma unroll
        for (int c = 0; c < 4; c++) s[nt][c] = 0.f;

    #pragma unroll
    for (int ks = 0; ks < 4; ks++) {
        const int kk = ks * 8 + ql;
        unsigned int a[4], b[7][2];
        a[0] = vA ? __float_as_uint(QSM(rA, kk))     : 0u;
        a[1] = vB ? __float_as_uint(QSM(rB, kk))     : 0u;
        a[2] = vA ? __float_as_uint(QSM(rA, kk + 4)) : 0u;
        a[3] = vB ? __float_as_uint(QSM(rB, kk + 4)) : 0u;
        #pragma unroll
        for (int nt = 0; nt < 7; nt++) {
            int c = nt * 8 + qr;
            b[nt][0] = __float_as_uint(ksm[c][kk]);
            b[nt][1] = __float_as_uint(ksm[c][kk + 4]);
        }
        #pragma unroll
        for (int nt = 0; nt < 7; nt++)
            mma_tf32(s[nt], a[0], a[1], a[2], a[3], b[nt][0], b[nt][1]);
    }

    __syncthreads();   // all warps done reading Q; usm becomes P storage

    // ---- bias + masks + softmax in fragments ----
    const float scale = 0.1767766952966369f;
    {
        const int iA = vA ? rA : 48;
        const int iB = vB ? rB : 48;
        const int xiA = iA / Pw, yiA = iA - xiA * Pw;
        const int xiB = iB / Pw, yiB = iB - xiB * Pw;

        #pragma unroll
        for (int nt = 0; nt < 7; nt++) {
            #pragma unroll
            for (int e = 0; e < 4; e++) {
                int j  = nt * 8 + ql * 2 + (e & 1);
                int xi = (e < 2) ? xiA : xiB;
                int yi = (e < 2) ? yiA : yiB;
                int r  = (e < 2) ? rA : rB;
                int jc = (j < PP) ? j : 48;
                int xj = jc / Pw, yj = jc - xj * Pw;
                float val = s[nt][e] * scale + psm[(xj - xi + 6) * 13 + (yj - yi + 6)];
                if (j >= PP) val = -1e30f;
                if (ul && ((r >= 28) != (j >= 28))) val = -1e30f;
                if (lr && ((yi >= 4) != (yj >= 4))) val = -1e30f;
                s[nt][e] = val;
            }
        }
        float mA = -1e30f, mB = -1e30f;
        #pragma unroll
        for (int nt = 0; nt < 7; nt++) {
            mA = fmaxf(mA, fmaxf(s[nt][0], s[nt][1]));
            mB = fmaxf(mB, fmaxf(s[nt][2], s[nt][3]));
        }
        mA = fmaxf(mA, __shfl_xor_sync(0xffffffffu, mA, 1));
        mA = fmaxf(mA, __shfl_xor_sync(0xffffffffu, mA, 2));
        mB = fmaxf(mB, __shfl_xor_sync(0xffffffffu, mB, 1));
        mB = fmaxf(mB, __shfl_xor_sync(0xffffffffu, mB, 2));

        float sA = 0.f, sB = 0.f;
        #pragma unroll
        for (int nt = 0; nt < 7; nt++) {
            s[nt][0] = __expf(s[nt][0] - mA);
            s[nt][1] = __expf(s[nt][1] - mA);
            s[nt][2] = __expf(s[nt][2] - mB);
            s[nt][3] = __expf(s[nt][3] - mB);
            sA += s[nt][0] + s[nt][1];
            sB += s[nt][2] + s[nt][3];
        }
        sA += __shfl_xor_sync(0xffffffffu, sA, 1);
        sA += __shfl_xor_sync(0xffffffffu, sA, 2);
        sB += __shfl_xor_sync(0xffffffffu, sB, 1);
        sB += __shfl_xor_sync(0xffffffffu, sB, 2);
        const float iAu = 1.0f / sA, iBu = 1.0f / sB;

        #pragma unroll
        for (int nt = 0; nt < 7; nt++) {
            int j0 = nt * 8 + ql * 2;
            if (vA) *(float2*)&SSM(rA, j0) = make_float2(s[nt][0] * iAu, s[nt][1] * iAu);
            if (vB) *(float2*)&SSM(rB, j0) = make_float2(s[nt][2] * iBu, s[nt][3] * iBu);
        }
    }
    __syncthreads();

    // coalesced attn write (fp32)
    float* aout = attn_out + (size_t)blk * PP * PP;
    for (int idx = tid; idx < PP * PP; idx += 128) {
        int r = idx / PP;
        aout[idx] = SSM(r, idx - r * PP);
    }

    // ---- O = P @ V ----
    float o[4][4];
    #pragma unroll
    for (int nt = 0; nt < 4; nt++)
        #pragma unroll
        for (int c = 0; c < 4; c++) o[nt][c] = 0.f;

    #pragma unroll
    for (int ks = 0; ks < 7; ks++) {
        const int kk = ks * 8 + ql;
        unsigned int a[4], b[4][2];
        a[0] = vA ? f2tf32(SSM(rA, kk))     : 0u;
        a[1] = vB ? f2tf32(SSM(rB, kk))     : 0u;
        a[2] = vA ? f2tf32(SSM(rA, kk + 4)) : 0u;
        a[3] = vB ? f2tf32(SSM(rB, kk + 4)) : 0u;
        #pragma unroll
        for (int nt = 0; nt < 4; nt++) {
            int c = nt * 8 + qr;
            b[nt][0] = __float_as_uint(vsm[kk][c]);
            b[nt][1] = __float_as_uint(vsm[kk + 4][c]);
        }
        #pragma unroll
        for (int nt = 0; nt < 4; nt++)
            mma_tf32(o[nt], a[0], a[1], a[2], a[3], b[nt][0], b[nt][1]);
    }

    float* ob = g_omid + (size_t)win * PP * INNER + head * 32;
    #pragma unroll
    for (int nt = 0; nt < 4; nt++) {
        int c = nt * 8 + ql * 2;
        if (vA)
            *(float2*)&ob[(size_t)rA * INNER + c] =
                make_float2(tf32r(o[nt][0]), tf32r(o[nt][1]));
        if (vB)
            *(float2*)&ob[(size_t)rB * INNER + c] =
                make_float2(tf32r(o[nt][2]), tf32r(o[nt][3]));
    }
}

// ---------------------------------------------------------------------------
// Kernel 4: out GEMM, tf32 TC, 3-stage cp.async + bias; result staged in smem
// (union with pipeline buffers) and scattered w-fastest (coalesced 28B runs).
// M=100352, N=128, K=256.
// ---------------------------------------------------------------------------
#define OA(st,r,k)  smbuf[(st) * 2560 + (r) * 20 + (k)]
#define OB(st,k,n)  smbuf[7680 + (st) * 2176 + (k) * 136 + (n)]
#define OSTG(r,c)   smbuf[(r) * 133 + (c)]

__global__ void out_gemm_tc(const float* __restrict__ b_out,
                            float* __restrict__ out)
{
    __shared__ float smbuf[17024];   // pipeline (14208) / staging (17024) union
    const unsigned int A_STRIDE = 2560 * 4;
    const unsigned int B_STRIDE = 2176 * 4;

    const int tid  = threadIdx.x;
    const int bm   = blockIdx.y * 128;
    const int lane = tid & 31, wid = tid >> 5;
    const int wm   = (wid & 1) * 64, wn = (wid >> 1) * 32;

    const int ar = tid & 127, ak = (tid >> 7) * 4;
    const float* agp = g_omid + (size_t)(bm + ar) * INNER + ak;
    const int bk = tid >> 4, bn8 = (tid & 15) * 8;
    const float* bgp = g_wout_t + (size_t)bk * 128 + bn8;

    unsigned int sA = (unsigned int)__cvta_generic_to_shared(&OA(0, ar, ak));
    unsigned int sB = (unsigned int)__cvta_generic_to_shared(&OB(0, bk, bn8));

    float acc[4][4][4];
    #pragma unroll
    for (int i = 0; i < 4; i++)
        #pragma unroll
        for (int j = 0; j < 4; j++)
            #pragma unroll
            for (int c = 0; c < 4; c++) acc[i][j][c] = 0.f;

    #pragma unroll
    for (int s = 0; s < 2; s++) {
        const int k0 = s * 16;
        cp16(sA + s * A_STRIDE,      agp + k0);
        cp16(sA + s * A_STRIDE + 32, agp + k0 + 8);
        cp16(sB + s * B_STRIDE,      bgp + (size_t)k0 * 128);
        cp16(sB + s * B_STRIDE + 16, bgp + (size_t)k0 * 128 + 4);
        cp_commit();
    }

    #pragma unroll
    for (int ks = 0; ks < 16; ks++) {
        if (ks < 15) cp_wait1(); else cp_wait0();
        __syncthreads();
        const int st = ks % 3;
        #pragma unroll
        for (int k8 = 0; k8 < 16; k8 += 8) {
            unsigned int af[4][4], bf[4][2];
            const int kk = k8 + (lane & 3);
            #pragma unroll
            for (int mt = 0; mt < 4; mt++) {
                int r = wm + mt * 16 + (lane >> 2);
                af[mt][0] = __float_as_uint(OA(st, r, kk));
                af[mt][1] = __float_as_uint(OA(st, r + 8, kk));
                af[mt][2] = __float_as_uint(OA(st, r, kk + 4));
                af[mt][3] = __float_as_uint(OA(st, r + 8, kk + 4));
            }
            #pragma unroll
            for (int nt = 0; nt < 4; nt++) {
                int c = wn + nt * 8 + (lane >> 2);
                bf[nt][0] = __float_as_uint(OB(st, kk, c));
                bf[nt][1] = __float_as_uint(OB(st, kk + 4, c));
            }
            #pragma unroll
            for (int mt = 0; mt < 4; mt++)
                #pragma unroll
                for (int nt = 0; nt < 4; nt++)
                    mma_tf32(acc[mt][nt], af[mt][0], af[mt][1], af[mt][2], af[mt][3],
                             bf[nt][0], bf[nt][1]);
        }
        __syncthreads();
        if (ks + 2 < 16) {
            const int snew = (ks + 2) % 3;
            const int k0 = (ks + 2) * 16;
            cp16(sA + snew * A_STRIDE,      agp + k0);
            cp16(sA + snew * A_STRIDE + 32, agp + k0 + 8);
            cp16(sB + snew * B_STRIDE,      bgp + (size_t)k0 * 128);
            cp16(sB + snew * B_STRIDE + 16, bgp + (size_t)k0 * 128 + 4);
            cp_commit();
        }
    }

    // ---- stage result (+bias) into smem union, then coalesced scatter ----
    __syncthreads();
    #pragma unroll
    for (int mt = 0; mt < 4; mt++) {
        #pragma unroll
        for (int half = 0; half < 2; half++) {
            int r = wm + mt * 16 + (lane >> 2) + half * 8;
            #pragma unroll
            for (int nt = 0; nt < 4; nt++) {
                int c = wn + nt * 8 + (lane & 3) * 2;
                OSTG(r, c)     = acc[mt][nt][half * 2 + 0] + b_out[c];
                OSTG(r, c + 1) = acc[mt][nt][half * 2 + 1] + b_out[c + 1];
            }
        }
    }
    __syncthreads();

    // w-fastest scatter: consecutive lanes -> consecutive window tokens
    for (int idx = tid; idx < 128 * 128; idx += 256) {
        int c  = idx >> 7;        // channel
        int sr = idx & 127;       // row in tile
        int r  = bm + sr;
        int win = r / PP;
        int t   = r - win * PP;
        int b   = win >> 6;
        int wl  = win & 63;
        int i1  = wl >> 3, i2 = wl & 7;
        int xx  = t / Pw,  yy = t - (t / Pw) * Pw;
        int h = i1 * Pw + xx + 3; if (h >= HW) h -= HW;
        int w = i2 * Pw + yy + 3; if (w >= HW) w -= HW;
        out[((size_t)b * 128 + c) * 3136 + h * HW + w] = OSTG(sr, c);
    }
}

// ---------------------------------------------------------------------------
extern "C" void kernel_launch(void* const* d_in, const int* in_sizes, int n_in,
                              void* d_out, int out_size)
{
    const float* x      = (const float*)d_in[0];
    const float* w_qkv  = (const float*)d_in[1];
    const float* w_out  = (const float*)d_in[2];
    const float* b_out  = (const float*)d_in[3];
    const float* pos    = (const float*)d_in[4];

    const long long O_ELEMS = (long long)Bb * Cc * HW * HW;
    const long long A_ELEMS = (long long)WINS * HEADS * PP * PP;

    float* outp = (float*)d_out;
    float* o_ptr;
    float* attn_ptr;

    if ((long long)out_size >= O_ELEMS + A_ELEMS) {
        o_ptr    = outp;
        attn_ptr = outp + O_ELEMS;
    } else if ((long long)out_size == A_ELEMS) {
        attn_ptr = outp;
        cudaGetSymbolAddress((void**)&o_ptr, g_o_dump);
    } else {
        o_ptr = outp;
        cudaGetSymbolAddress((void**)&attn_ptr, g_attn_dump);
    }

    transpose_w<<<512, 256>>>(w_qkv, w_out);
    gather_x<<<Bb * 49, 256>>>(x);
    qkv_gemm_tc<<<dim3(768 / 128, MROWS / 128), 256>>>();
    attn_tc_kernel<<<WINS * HEADS, 128>>>(pos, attn_ptr);
    out_gemm_tc<<<dim3(1, MROWS / 128), 256>>>(b_out, o_ptr);
}